// round 9
// baseline (speedup 1.0000x reference)
#include <cuda_runtime.h>
#include <cstdint>

// Problem dims (fixed by the reference)
#define T_STEPS 512
#define BATCH   256
#define DIN     128
#define DH      512
#define DOUT    128

// Persistent recurrence: 8 row-blocks x 16 col-blocks of 32x32 tiles
#define NCTA        128
#define REC_THREADS 256

// SMEM layout strides (floats)
#define W_STRIDE 672   // 640 k (512 W1h + 128 W1x) + shift headroom; 672 % 32 == 0
#define H_STRIDE 644   // 640 k + pad; 644 % 32 == 4
#define REC_SMEM_FLOATS (32 * W_STRIDE + 32 * H_STRIDE)

typedef unsigned long long ull;

// -------------------- device scratch (no allocation allowed) --------------------
__device__ float    g_h[2][BATCH * DH];        // ping-pong hidden state
__device__ unsigned g_flag[T_STEPS * NCTA];    // per-(step,tile) ready flags

// -------------------- asm helpers --------------------
__device__ __forceinline__ ull fma2(ull a, ull b, ull c) {
    ull d;
    asm("fma.rn.f32x2 %0, %1, %2, %3;" : "=l"(d) : "l"(a), "l"(b), "l"(c));
    return d;
}
__device__ __forceinline__ float sum2(ull v) {
    float lo, hi;
    asm("mov.b64 {%0, %1}, %2;" : "=f"(lo), "=f"(hi) : "l"(v));
    return lo + hi;
}
__device__ __forceinline__ unsigned ld_acquire(const unsigned* p) {
    unsigned v;
    asm volatile("ld.acquire.gpu.global.u32 %0, [%1];" : "=r"(v) : "l"(p) : "memory");
    return v;
}
__device__ __forceinline__ void st_release(unsigned* p, unsigned v) {
    asm volatile("st.release.gpu.global.u32 [%0], %1;" :: "l"(p), "r"(v) : "memory");
}

// -------------------- reset (runs every replay: determinism) --------------------
// 256 blocks x 256 threads = 65536 threads: zero all flags (512*128) + h0 (131072).
__global__ void reset_kernel() {
    int idx = blockIdx.x * blockDim.x + threadIdx.x;
    g_flag[idx] = 0u;
    g_h[0][idx * 2 + 0] = 0.0f;
    g_h[0][idx * 2 + 1] = 0.0f;
}

// -------------------- fused persistent recurrence --------------------
// CTA (rb,cb) owns output tile h[rb*32:+32][cb*32:+32].
// SMEM-resident, k-transposed (+shift 4*(c>>2)) weight block of 640 k:
//   k 0..511   = W1h[:, col0:+32]
//   k 512..639 = W1x[:, col0:+32]   (xproj fused as a 5th k-chunk)
// Per step: xs chunk first (no dependency -> absorbs producer drain latency),
// then 4 h chunks with per-chunk flag waits + LDG latency hidden under GEMM halves.
__global__ void __launch_bounds__(REC_THREADS, 1)
rec_kernel(const float* __restrict__ xs, const float* __restrict__ W1x,
           const float* __restrict__ W1h, const float* __restrict__ b1p) {
    extern __shared__ float sm[];
    float* w_smT = sm;                    // [32 cols][672], col c shifted by 4*(c>>2)
    float* h_sm  = sm + 32 * W_STRIDE;    // [32 rows][644]; k 512..639 = xs tile

    const int tid  = threadIdx.x;
    const int bid  = blockIdx.x;
    const int cb   = bid & 15;
    const int rb   = bid >> 4;
    const int col0 = cb * 32;
    const int row0 = rb * 32;

    // Compute layout: warp = 16 rows x 2 col-groups (crossbar-economical)
    const int l  = tid & 31;
    const int ww = tid >> 5;
    const int ty = ((ww & 1) << 4) + (l >> 1);       // 0..31 row
    const int tx = (l & 1) + ((ww >> 1) << 1);       // 0..7 col-group of 4

    // Restage layout: row rr, 64B segment gg
    const int rr = tid >> 3;
    const int gg = tid & 7;

    // Prologue: stage W1h^T (k 0..511)
#pragma unroll
    for (int i = 0; i < 16; i++) {
        int idx = i * REC_THREADS + tid;             // 0..4095
        int c4  = idx & 7;
        int k   = idx >> 3;
        float4 v = *reinterpret_cast<const float4*>(W1h + (size_t)k * DH + col0 + c4 * 4);
        float* bp = w_smT + 4 * c4 + k;              // shift = 4*(c>>2) = 4*c4
        bp[(4 * c4 + 0) * W_STRIDE] = v.x;
        bp[(4 * c4 + 1) * W_STRIDE] = v.y;
        bp[(4 * c4 + 2) * W_STRIDE] = v.z;
        bp[(4 * c4 + 3) * W_STRIDE] = v.w;
    }
    // Prologue: stage W1x^T (k 512..639)
#pragma unroll
    for (int i = 0; i < 4; i++) {
        int idx = i * REC_THREADS + tid;             // 0..1023
        int c4  = idx & 7;
        int k   = idx >> 3;                          // 0..127
        float4 v = *reinterpret_cast<const float4*>(W1x + (size_t)k * DH + col0 + c4 * 4);
        float* bp = w_smT + 4 * c4 + 512 + k;
        bp[(4 * c4 + 0) * W_STRIDE] = v.x;
        bp[(4 * c4 + 1) * W_STRIDE] = v.y;
        bp[(4 * c4 + 2) * W_STRIDE] = v.z;
        bp[(4 * c4 + 3) * W_STRIDE] = v.w;
    }
    const float bias = b1p[0];
    __syncthreads();

    const float* hrow = h_sm + (size_t)ty * H_STRIDE;
    const float* wp0  = w_smT + (size_t)(4 * tx + 0) * W_STRIDE + 4 * tx;
    const float* wp1  = w_smT + (size_t)(4 * tx + 1) * W_STRIDE + 4 * tx;
    const float* wp2  = w_smT + (size_t)(4 * tx + 2) * W_STRIDE + 4 * tx;
    const float* wp3  = w_smT + (size_t)(4 * tx + 3) * W_STRIDE + 4 * tx;

    const float* hin  = g_h[0];
    float*       hout = g_h[1];
    const int    base = cb >> 2;          // rotated chunk start

    for (int s = 0; s < T_STEPS; s++) {
        ull a0 = 0ull, a1 = 0ull, a2 = 0ull, a3 = 0ull;

        // 128-k GEMM slice, packed f32x2; len is a literal at every call site.
        auto gemm = [&](int k0, int len) {
#pragma unroll 4
            for (int kk = 0; kk < len; kk += 4) {
                int k = k0 + kk;
                ulonglong2 h2 = *reinterpret_cast<const ulonglong2*>(hrow + k);
                ulonglong2 v0 = *reinterpret_cast<const ulonglong2*>(wp0 + k);
                ulonglong2 v1 = *reinterpret_cast<const ulonglong2*>(wp1 + k);
                ulonglong2 v2 = *reinterpret_cast<const ulonglong2*>(wp2 + k);
                ulonglong2 v3 = *reinterpret_cast<const ulonglong2*>(wp3 + k);
                a0 = fma2(h2.x, v0.x, a0); a0 = fma2(h2.y, v0.y, a0);
                a1 = fma2(h2.x, v1.x, a1); a1 = fma2(h2.y, v1.y, a1);
                a2 = fma2(h2.x, v2.x, a2); a2 = fma2(h2.y, v2.y, a2);
                a3 = fma2(h2.x, v3.x, a3); a3 = fma2(h2.y, v3.y, a3);
            }
        };

        // ---- xs chunk (k 512..639): no dependency, stage immediately ----
        {
            const float* xrow = xs + ((size_t)s * BATCH + row0 + rr) * DIN + gg * 16;
            float4 q0 = __ldg(reinterpret_cast<const float4*>(xrow + 0));
            float4 q1 = __ldg(reinterpret_cast<const float4*>(xrow + 4));
            float4 q2 = __ldg(reinterpret_cast<const float4*>(xrow + 8));
            float4 q3 = __ldg(reinterpret_cast<const float4*>(xrow + 12));
            float* d = h_sm + (size_t)rr * H_STRIDE + 512 + gg * 16;
            *reinterpret_cast<float4*>(d + 0)  = q0;
            *reinterpret_cast<float4*>(d + 4)  = q1;
            *reinterpret_cast<float4*>(d + 8)  = q2;
            *reinterpret_cast<float4*>(d + 12) = q3;
        }
        __syncthreads();

        // ---- wait first h chunk's 4 producers ----
        const int c0 = base;
        if (s > 0 && tid < 4) {
            const unsigned* f = &g_flag[(s - 1) * NCTA + rb * 16 + c0 * 4 + tid];
            while (ld_acquire(f) == 0u) { }
        }
        __syncthreads();

        // LDG chunk c0 into regs; xs-chunk GEMM hides the L2 latency.
        float4 r0, r1, r2, r3;
        {
            const float* srow = hin + (size_t)(row0 + rr) * DH + c0 * 128 + gg * 16;
            r0 = __ldcg(reinterpret_cast<const float4*>(srow + 0));
            r1 = __ldcg(reinterpret_cast<const float4*>(srow + 4));
            r2 = __ldcg(reinterpret_cast<const float4*>(srow + 8));
            r3 = __ldcg(reinterpret_cast<const float4*>(srow + 12));
        }
        gemm(512, 128);                              // xs @ W1x
        {
            float* d = h_sm + (size_t)rr * H_STRIDE + c0 * 128 + gg * 16;
            *reinterpret_cast<float4*>(d + 0)  = r0;
            *reinterpret_cast<float4*>(d + 4)  = r1;
            *reinterpret_cast<float4*>(d + 8)  = r2;
            *reinterpret_cast<float4*>(d + 12) = r3;
        }
        __syncthreads();

        // ---- h chunks, software-pipelined ----
#pragma unroll
        for (int j = 0; j < 3; j++) {
            const int cj = (base + j) & 3;
            const int cn = (base + j + 1) & 3;
            const int kb = cj * 128;
            gemm(kb, 64);                            // first half of current chunk
            if (s > 0 && tid < 4) {                  // producers long done by now
                const unsigned* f = &g_flag[(s - 1) * NCTA + rb * 16 + cn * 4 + tid];
                while (ld_acquire(f) == 0u) { }
            }
            __syncthreads();
            {
                const float* srow = hin + (size_t)(row0 + rr) * DH + cn * 128 + gg * 16;
                r0 = __ldcg(reinterpret_cast<const float4*>(srow + 0));
                r1 = __ldcg(reinterpret_cast<const float4*>(srow + 4));
                r2 = __ldcg(reinterpret_cast<const float4*>(srow + 8));
                r3 = __ldcg(reinterpret_cast<const float4*>(srow + 12));
            }
            gemm(kb + 64, 64);                       // hides the LDG above
            {
                float* d = h_sm + (size_t)rr * H_STRIDE + cn * 128 + gg * 16;
                *reinterpret_cast<float4*>(d + 0)  = r0;
                *reinterpret_cast<float4*>(d + 4)  = r1;
                *reinterpret_cast<float4*>(d + 8)  = r2;
                *reinterpret_cast<float4*>(d + 12) = r3;
            }
            __syncthreads();
        }
        {
            const int c3 = (base + 3) & 3;
            gemm(c3 * 128, 128);
        }

        // ---- epilogue ----
        float4 o;
        o.x = tanhf(sum2(a0) + bias);
        o.y = tanhf(sum2(a1) + bias);
        o.z = tanhf(sum2(a2) + bias);
        o.w = tanhf(sum2(a3) + bias);
        *reinterpret_cast<float4*>(hout + (size_t)(row0 + ty) * DH + col0 + 4 * tx) = o;

        if (s < T_STEPS - 1) {
            __syncthreads();                          // all tile stores issued
            if (tid == 0) st_release(&g_flag[s * NCTA + bid], 1u);
        }
        const float* t = hin; hin = hout; hout = const_cast<float*>(t);
    }
    // 512 steps (even): final h lives in g_h[0].
}

// -------------------- out = h_final @ W2 + b2 --------------------
// 32 CTAs x 256 threads, 8 batch rows per CTA: each W2 value reused 8x.
__global__ void __launch_bounds__(256) out_kernel(const float* __restrict__ W2,
                                                  const float* __restrict__ b2p,
                                                  float* __restrict__ out) {
    __shared__ float hs[8 * DH];
    const int tid = threadIdx.x;
    const int rb8 = blockIdx.x * 8;
#pragma unroll
    for (int i = 0; i < 4; i++) {
        int idx = i * 256 + tid;                     // 1024 float4
        int r = idx >> 7, c4 = idx & 127;
        float4 v = __ldcg(reinterpret_cast<const float4*>(
            &g_h[0][(size_t)(rb8 + r) * DH + c4 * 4]));
        *reinterpret_cast<float4*>(&hs[r * DH + c4 * 4]) = v;
    }
    __syncthreads();

    const int o    = tid & 127;
    const int half = tid >> 7;                       // rows 4*half .. 4*half+3
    const float* h0 = hs + (4 * half + 0) * DH;
    const float* h1 = hs + (4 * half + 1) * DH;
    const float* h2 = hs + (4 * half + 2) * DH;
    const float* h3 = hs + (4 * half + 3) * DH;
    const float b = b2p[0];
    float acc0 = b, acc1 = b, acc2 = b, acc3 = b;
#pragma unroll 8
    for (int k = 0; k < DH; k++) {
        float w = __ldg(W2 + (size_t)k * DOUT + o);
        acc0 += h0[k] * w; acc1 += h1[k] * w; acc2 += h2[k] * w; acc3 += h3[k] * w;
    }
    out[(size_t)(rb8 + 4 * half + 0) * DOUT + o] = acc0;
    out[(size_t)(rb8 + 4 * half + 1) * DOUT + o] = acc1;
    out[(size_t)(rb8 + 4 * half + 2) * DOUT + o] = acc2;
    out[(size_t)(rb8 + 4 * half + 3) * DOUT + o] = acc3;
}

// -------------------- launch --------------------
extern "C" void kernel_launch(void* const* d_in, const int* in_sizes, int n_in,
                              void* d_out, int out_size) {
    const float* xs  = (const float*)d_in[0];
    const float* W1x = (const float*)d_in[1];
    const float* W1h = (const float*)d_in[2];
    const float* b1  = (const float*)d_in[3];
    const float* W2  = (const float*)d_in[4];
    const float* b2  = (const float*)d_in[5];
    float* out = (float*)d_out;

    (void)in_sizes; (void)n_in; (void)out_size;

    cudaFuncSetAttribute(rec_kernel, cudaFuncAttributeMaxDynamicSharedMemorySize,
                         REC_SMEM_FLOATS * (int)sizeof(float));

    reset_kernel<<<256, 256>>>();
    rec_kernel<<<NCTA, REC_THREADS, REC_SMEM_FLOATS * sizeof(float)>>>(xs, W1x, W1h, b1);
    out_kernel<<<32, 256>>>(W2, b2, out);
}